// round 5
// baseline (speedup 1.0000x reference)
#include <cuda_runtime.h>
#include <cstdint>

// ============================================================================
// FeedForwardLoRA on GB300 (sm_103) — tf32 mma.sync path.
// tcgen05 is unavailable: the harness emits compute_103 PTX (no 'a' feature
// target), so all tcgen05.* ops are rejected by ptxas. mma.sync.m16n8k8.tf32
// is plain sm_80+ PTX and runs on the Blackwell tensor pipe.
//
//   W1e = rna_tf32(W1 + 0.25 * B1[a] @ A1[a])
//   W2e = rna_tf32(W2 + 0.25 * B2[a] @ A2[a])
//   xr  = rna_tf32(x)
//   h   = rna_tf32(relu(xr @ W1e^T))     GEMM1: M=16384 N=4096 K=1024
//   out = h @ W2e^T                      GEMM2: M=16384 N=1024 K=4096
// ============================================================================

#define TOK     16384
#define DMODEL  1024
#define DFF     4096
#define RANKL   4

#define TM   128          // CTA M tile
#define TN   256          // CTA N tile
#define TKC  32           // K chunk
#define NS   3            // cp.async pipeline stages
#define PITCH 36          // smem row pitch in floats (skew-4 -> conflict-free)

#define SM_A_WORDS (TM * PITCH)                 // 4608 floats
#define SM_B_WORDS (TN * PITCH)                 // 9216 floats
#define STAGE_WORDS (SM_A_WORDS + SM_B_WORDS)   // 13824 floats = 55296 B
#define SMEM_TOTAL (NS * STAGE_WORDS * 4)       // 165888 B

// ---------------------------------------------------------------------------
// Scratch (static __device__ arrays — the sanctioned no-alloc workaround)
// ---------------------------------------------------------------------------
__device__ float g_xr[(size_t)TOK * DMODEL];    //  64 MB
__device__ float g_h [(size_t)TOK * DFF];       // 256 MB
__device__ float g_w1[(size_t)DFF * DMODEL];    //  16 MB
__device__ float g_w2[(size_t)DMODEL * DFF];    //  16 MB

// ---------------------------------------------------------------------------
// Helpers
// ---------------------------------------------------------------------------
__device__ __forceinline__ uint32_t smem_u32(const void* p) {
    uint32_t a;
    asm("{ .reg .u64 t; cvta.to.shared.u64 t, %1; cvt.u32.u64 %0, t; }"
        : "=r"(a) : "l"(p));
    return a;
}

__device__ __forceinline__ float rna_tf32(float v) {
    uint32_t o;
    asm("cvt.rna.tf32.f32 %0, %1;" : "=r"(o) : "f"(v));
    return __uint_as_float(o);
}

#define CPA16(smem_addr, gptr) \
    asm volatile("cp.async.cg.shared.global [%0], [%1], 16;" \
                 :: "r"(smem_addr), "l"(gptr))
#define CP_COMMIT()  asm volatile("cp.async.commit_group;" ::: "memory")
#define CP_WAIT_1()  asm volatile("cp.async.wait_group 1;" ::: "memory")   // NS-2

// D += A * B   (m16n8k8, tf32 inputs, fp32 accumulate)
__device__ __forceinline__ void mma8(float* d, const float* a, const float* b) {
    asm volatile(
        "mma.sync.aligned.m16n8k8.row.col.f32.tf32.tf32.f32 "
        "{%0,%1,%2,%3}, {%4,%5,%6,%7}, {%8,%9}, {%0,%1,%2,%3};"
        : "+f"(d[0]), "+f"(d[1]), "+f"(d[2]), "+f"(d[3])
        : "r"(__float_as_uint(a[0])), "r"(__float_as_uint(a[1])),
          "r"(__float_as_uint(a[2])), "r"(__float_as_uint(a[3])),
          "r"(__float_as_uint(b[0])), "r"(__float_as_uint(b[1])));
}

// ---------------------------------------------------------------------------
// GEMM: C[M, Nglob] = op(A[M,K] @ B[Nglob,K]^T).  op = relu+rna or identity.
// Grid (Nglob/TN, M/TM), 256 threads = 8 warps of 64x64 tiles (2 x 4 layout).
// All dims divide exactly — no tails anywhere.
// ---------------------------------------------------------------------------
template <bool RELU_RNA>
__global__ void __launch_bounds__(256, 1)
gemm_tf32(const float* __restrict__ Ag, const float* __restrict__ Bg,
          float* __restrict__ Cg, int K, int KT, int Nglob)
{
    extern __shared__ float smem[];
    const uint32_t sbase = smem_u32(smem);
    const int tid = threadIdx.x;
    const int m0 = blockIdx.y * TM;
    const int n0 = blockIdx.x * TN;

    // ---- async-load geometry: thread -> (row, 16B chunk) --------------------
    const int lrow = tid >> 3;          // 0..31
    const int lchk = tid & 7;           // 0..7  (16B units across the 128B row)

    auto load_stage = [&](int slot, int kt) {
        const uint32_t sw = sbase + (uint32_t)(slot * STAGE_WORDS) * 4u;
        const size_t kofs = (size_t)kt * TKC + lchk * 4;
        const uint32_t cofs = (uint32_t)(lchk * 4) * 4u;
#pragma unroll
        for (int j = 0; j < 4; j++) {                       // A: 128 rows
            const int r = lrow + 32 * j;
            CPA16(sw + (uint32_t)(r * PITCH) * 4u + cofs,
                  Ag + (size_t)(m0 + r) * K + kofs);
        }
#pragma unroll
        for (int j = 0; j < 8; j++) {                       // B: 256 rows
            const int r = lrow + 32 * j;
            CPA16(sw + (uint32_t)(SM_A_WORDS + r * PITCH) * 4u + cofs,
                  Bg + (size_t)(n0 + r) * K + kofs);
        }
    };

    // ---- compute geometry ---------------------------------------------------
    const int lane = tid & 31;
    const int w = tid >> 5;
    const int wm = (w & 1) * 64;        // warp M offset within CTA tile
    const int wn = (w >> 1) * 64;       // warp N offset
    const int g = lane >> 2;            // fragment group (row within 8)
    const int c = lane & 3;             // fragment thread-in-group (k within 4)

    float acc[4][8][4];
#pragma unroll
    for (int mi = 0; mi < 4; mi++)
#pragma unroll
        for (int ni = 0; ni < 8; ni++)
#pragma unroll
            for (int q = 0; q < 4; q++) acc[mi][ni][q] = 0.0f;

    // ---- prologue: stages 0..NS-2 -------------------------------------------
#pragma unroll
    for (int s = 0; s < NS - 1; s++) {
        load_stage(s, s);
        CP_COMMIT();
    }

    // ---- main loop ----------------------------------------------------------
    for (int kt = 0; kt < KT; kt++) {
        CP_WAIT_1();                    // stage kt landed
        __syncthreads();                // visible to all; prior compute retired

        const int pf = kt + NS - 1;
        if (pf < KT) load_stage(pf % NS, pf);
        CP_COMMIT();                    // empty group on tail keeps counts sane

        const float* sA = smem + (kt % NS) * STAGE_WORDS;
        const float* sB = sA + SM_A_WORDS;

#pragma unroll
        for (int ks = 0; ks < 4; ks++) {            // 4 x k8 = K chunk 32
            float a[4][4];
            float b[8][2];
#pragma unroll
            for (int mi = 0; mi < 4; mi++) {
                const float* p = sA + (wm + mi * 16 + g) * PITCH + ks * 8 + c;
                a[mi][0] = p[0];
                a[mi][2] = p[4];
                a[mi][1] = p[8 * PITCH];
                a[mi][3] = p[8 * PITCH + 4];
            }
#pragma unroll
            for (int ni = 0; ni < 8; ni++) {
                const float* p = sB + (wn + ni * 8 + g) * PITCH + ks * 8 + c;
                b[ni][0] = p[0];
                b[ni][1] = p[4];
            }
#pragma unroll
            for (int mi = 0; mi < 4; mi++)
#pragma unroll
                for (int ni = 0; ni < 8; ni++)
                    mma8(acc[mi][ni], a[mi], b[ni]);
        }
    }

    // ---- epilogue: direct stores (float2 per fragment half) -----------------
#pragma unroll
    for (int mi = 0; mi < 4; mi++) {
        const int r0 = m0 + wm + mi * 16 + g;
        const int r1 = r0 + 8;
#pragma unroll
        for (int ni = 0; ni < 8; ni++) {
            const int cc = n0 + wn + ni * 8 + 2 * c;
            float2 v0 = make_float2(acc[mi][ni][0], acc[mi][ni][1]);
            float2 v1 = make_float2(acc[mi][ni][2], acc[mi][ni][3]);
            if (RELU_RNA) {
                v0.x = rna_tf32(fmaxf(v0.x, 0.0f));
                v0.y = rna_tf32(fmaxf(v0.y, 0.0f));
                v1.x = rna_tf32(fmaxf(v1.x, 0.0f));
                v1.y = rna_tf32(fmaxf(v1.y, 0.0f));
            }
            *(float2*)(Cg + (size_t)r0 * Nglob + cc) = v0;
            *(float2*)(Cg + (size_t)r1 * Nglob + cc) = v1;
        }
    }
}

// ---------------------------------------------------------------------------
// Weight merge: Wm = rna_tf32(W + 0.25 * B[a] @ A[a]),  W:[OUT,IN] row-major
// ---------------------------------------------------------------------------
__global__ void merge_w(const float* __restrict__ W, const float* __restrict__ A,
                        const float* __restrict__ Bm, const int* __restrict__ aid,
                        float* __restrict__ Wm, int OUT, int IN)
{
    const int in4 = IN >> 2;
    const int i = blockIdx.x * blockDim.x + threadIdx.x;
    if (i >= OUT * in4) return;
    const int f = i / in4;
    const int d = (i - f * in4) << 2;
    const int a = aid[0];

    const float* Aa = A + (size_t)a * RANKL * IN;
    const float* Ba = Bm + (size_t)a * OUT * RANKL + (size_t)f * RANKL;
    const float b0 = Ba[0] * 0.25f, b1 = Ba[1] * 0.25f,
                b2 = Ba[2] * 0.25f, b3 = Ba[3] * 0.25f;

    float4 w = ((const float4*)W)[i];
    const float4 a0 = *(const float4*)(Aa + 0 * (size_t)IN + d);
    const float4 a1 = *(const float4*)(Aa + 1 * (size_t)IN + d);
    const float4 a2 = *(const float4*)(Aa + 2 * (size_t)IN + d);
    const float4 a3 = *(const float4*)(Aa + 3 * (size_t)IN + d);

    w.x = rna_tf32(w.x + b0 * a0.x + b1 * a1.x + b2 * a2.x + b3 * a3.x);
    w.y = rna_tf32(w.y + b0 * a0.y + b1 * a1.y + b2 * a2.y + b3 * a3.y);
    w.z = rna_tf32(w.z + b0 * a0.z + b1 * a1.z + b2 * a2.z + b3 * a3.z);
    w.w = rna_tf32(w.w + b0 * a0.w + b1 * a1.w + b2 * a2.w + b3 * a3.w);
    ((float4*)Wm)[i] = w;
}

// ---------------------------------------------------------------------------
// Activation pre-round: xr = rna_tf32(x)
// ---------------------------------------------------------------------------
__global__ void rna_copy(const float4* __restrict__ in, float4* __restrict__ out,
                         int n4)
{
    const int i = blockIdx.x * blockDim.x + threadIdx.x;
    if (i >= n4) return;
    float4 v = in[i];
    v.x = rna_tf32(v.x); v.y = rna_tf32(v.y);
    v.z = rna_tf32(v.z); v.w = rna_tf32(v.w);
    out[i] = v;
}

// ---------------------------------------------------------------------------
// Launch
// ---------------------------------------------------------------------------
extern "C" void kernel_launch(void* const* d_in, const int* in_sizes, int n_in,
                              void* d_out, int out_size)
{
    const float* x   = (const float*)d_in[0];
    const float* W1  = (const float*)d_in[1];
    const float* A1  = (const float*)d_in[2];
    const float* B1  = (const float*)d_in[3];
    const float* W2  = (const float*)d_in[4];
    const float* A2  = (const float*)d_in[5];
    const float* B2  = (const float*)d_in[6];
    const int*   aid = (const int*)d_in[7];
    float* out = (float*)d_out;

    float *xr, *h, *w1, *w2;
    cudaGetSymbolAddress((void**)&xr, g_xr);
    cudaGetSymbolAddress((void**)&h,  g_h);
    cudaGetSymbolAddress((void**)&w1, g_w1);
    cudaGetSymbolAddress((void**)&w2, g_w2);

    cudaFuncSetAttribute(gemm_tf32<true>,
                         cudaFuncAttributeMaxDynamicSharedMemorySize, SMEM_TOTAL);
    cudaFuncSetAttribute(gemm_tf32<false>,
                         cudaFuncAttributeMaxDynamicSharedMemorySize, SMEM_TOTAL);

    // 1) round x to tf32 (rna)
    const int n4x = TOK * DMODEL / 4;
    rna_copy<<<(n4x + 255) / 256, 256>>>((const float4*)x, (float4*)xr, n4x);

    // 2) fold LoRA into weights + rna round
    const int n4w = DFF * DMODEL / 4;
    merge_w<<<(n4w + 255) / 256, 256>>>(W1, A1, B1, aid, w1, DFF, DMODEL);
    merge_w<<<(n4w + 255) / 256, 256>>>(W2, A2, B2, aid, w2, DMODEL, DFF);

    // 3) h = rna(relu(xr @ w1^T))      M=16384, N=4096, K=1024
    dim3 g1(DFF / TN, TOK / TM);
    gemm_tf32<true><<<g1, 256, SMEM_TOTAL>>>(xr, w1, h, DMODEL, DMODEL / TKC, DFF);

    // 4) out = h @ w2^T                M=16384, N=1024, K=4096
    dim3 g2(DMODEL / TN, TOK / TM);
    gemm_tf32<false><<<g2, 256, SMEM_TOTAL>>>(h, w2, out, DFF, DFF / TKC, DMODEL);
}

// round 6
// speedup vs baseline: 1.5797x; 1.5797x over previous
#include <cuda_runtime.h>
#include <cstdint>

// ============================================================================
// FeedForwardLoRA on GB300 (sm_103) — tf32 mma.sync path, R6.
// R5 passed @2587us: tensor=56%, occ=12.4% (1 CTA/SM), memory cold.
// R6: CTA tile 128x256 -> 128x128 so 2 CTAs co-reside per SM (smem 110.6KB/CTA,
// regs capped at 128 via __launch_bounds__(256,2)) to cover the per-chunk
// barrier/latency gaps that idle the tensor pipe at occupancy 1.
//
//   W1e = rna_tf32(W1 + 0.25 * B1[a] @ A1[a])
//   W2e = rna_tf32(W2 + 0.25 * B2[a] @ A2[a])
//   xr  = rna_tf32(x)
//   h   = rna_tf32(relu(xr @ W1e^T))     GEMM1: M=16384 N=4096 K=1024
//   out = h @ W2e^T                      GEMM2: M=16384 N=1024 K=4096
// ============================================================================

#define TOK     16384
#define DMODEL  1024
#define DFF     4096
#define RANKL   4

#define TM   128          // CTA M tile
#define TN   128          // CTA N tile
#define TKC  32           // K chunk
#define NS   3            // cp.async pipeline stages
#define PITCH 36          // smem row pitch in floats (skew-4 -> conflict-free)

#define SM_A_WORDS (TM * PITCH)                 // 4608 floats
#define SM_B_WORDS (TN * PITCH)                 // 4608 floats
#define STAGE_WORDS (SM_A_WORDS + SM_B_WORDS)   // 9216 floats = 36864 B
#define SMEM_TOTAL (NS * STAGE_WORDS * 4)       // 110592 B  (x2 CTAs = 221184/SM)

// ---------------------------------------------------------------------------
// Scratch (static __device__ arrays — the sanctioned no-alloc workaround)
// ---------------------------------------------------------------------------
__device__ float g_xr[(size_t)TOK * DMODEL];    //  64 MB
__device__ float g_h [(size_t)TOK * DFF];       // 256 MB
__device__ float g_w1[(size_t)DFF * DMODEL];    //  16 MB
__device__ float g_w2[(size_t)DMODEL * DFF];    //  16 MB

// ---------------------------------------------------------------------------
// Helpers
// ---------------------------------------------------------------------------
__device__ __forceinline__ uint32_t smem_u32(const void* p) {
    uint32_t a;
    asm("{ .reg .u64 t; cvta.to.shared.u64 t, %1; cvt.u32.u64 %0, t; }"
        : "=r"(a) : "l"(p));
    return a;
}

__device__ __forceinline__ float rna_tf32(float v) {
    uint32_t o;
    asm("cvt.rna.tf32.f32 %0, %1;" : "=r"(o) : "f"(v));
    return __uint_as_float(o);
}

#define CPA16(smem_addr, gptr) \
    asm volatile("cp.async.cg.shared.global [%0], [%1], 16;" \
                 :: "r"(smem_addr), "l"(gptr))
#define CP_COMMIT()  asm volatile("cp.async.commit_group;" ::: "memory")
#define CP_WAIT_1()  asm volatile("cp.async.wait_group 1;" ::: "memory")   // NS-2

// D += A * B   (m16n8k8, tf32 inputs, fp32 accumulate)
__device__ __forceinline__ void mma8(float* d, const float* a, const float* b) {
    asm volatile(
        "mma.sync.aligned.m16n8k8.row.col.f32.tf32.tf32.f32 "
        "{%0,%1,%2,%3}, {%4,%5,%6,%7}, {%8,%9}, {%0,%1,%2,%3};"
        : "+f"(d[0]), "+f"(d[1]), "+f"(d[2]), "+f"(d[3])
        : "r"(__float_as_uint(a[0])), "r"(__float_as_uint(a[1])),
          "r"(__float_as_uint(a[2])), "r"(__float_as_uint(a[3])),
          "r"(__float_as_uint(b[0])), "r"(__float_as_uint(b[1])));
}

// ---------------------------------------------------------------------------
// GEMM: C[M, Nglob] = op(A[M,K] @ B[Nglob,K]^T).  op = relu+rna or identity.
// Grid (Nglob/TN, M/TM), 256 threads = 8 warps of 64x32 tiles (2 x 4 layout).
// 2 CTAs per SM. All dims divide exactly — no tails anywhere.
// ---------------------------------------------------------------------------
template <bool RELU_RNA>
__global__ void __launch_bounds__(256, 2)
gemm_tf32(const float* __restrict__ Ag, const float* __restrict__ Bg,
          float* __restrict__ Cg, int K, int KT, int Nglob)
{
    extern __shared__ float smem[];
    const uint32_t sbase = smem_u32(smem);
    const int tid = threadIdx.x;
    const int m0 = blockIdx.y * TM;
    const int n0 = blockIdx.x * TN;

    // ---- async-load geometry: thread -> (row, 16B chunk) --------------------
    const int lrow = tid >> 3;          // 0..31
    const int lchk = tid & 7;           // 0..7  (16B units across the 128B row)

    auto load_stage = [&](int slot, int kt) {
        const uint32_t sw = sbase + (uint32_t)(slot * STAGE_WORDS) * 4u;
        const size_t kofs = (size_t)kt * TKC + lchk * 4;
        const uint32_t cofs = (uint32_t)(lchk * 4) * 4u;
#pragma unroll
        for (int j = 0; j < 4; j++) {                       // A: 128 rows
            const int r = lrow + 32 * j;
            CPA16(sw + (uint32_t)(r * PITCH) * 4u + cofs,
                  Ag + (size_t)(m0 + r) * K + kofs);
        }
#pragma unroll
        for (int j = 0; j < 4; j++) {                       // B: 128 rows
            const int r = lrow + 32 * j;
            CPA16(sw + (uint32_t)(SM_A_WORDS + r * PITCH) * 4u + cofs,
                  Bg + (size_t)(n0 + r) * K + kofs);
        }
    };

    // ---- compute geometry ---------------------------------------------------
    const int lane = tid & 31;
    const int w = tid >> 5;
    const int wm = (w & 1) * 64;        // warp M offset within CTA tile
    const int wn = (w >> 1) * 32;       // warp N offset
    const int g = lane >> 2;            // fragment group (row within 8)
    const int c = lane & 3;             // fragment thread-in-group (k within 4)

    float acc[4][4][4];
#pragma unroll
    for (int mi = 0; mi < 4; mi++)
#pragma unroll
        for (int ni = 0; ni < 4; ni++)
#pragma unroll
            for (int q = 0; q < 4; q++) acc[mi][ni][q] = 0.0f;

    // ---- prologue: stages 0..NS-2 -------------------------------------------
#pragma unroll
    for (int s = 0; s < NS - 1; s++) {
        load_stage(s, s);
        CP_COMMIT();
    }

    // ---- main loop ----------------------------------------------------------
    for (int kt = 0; kt < KT; kt++) {
        CP_WAIT_1();                    // stage kt landed
        __syncthreads();                // visible to all; prior compute retired

        const int pf = kt + NS - 1;
        if (pf < KT) load_stage(pf % NS, pf);
        CP_COMMIT();                    // empty group on tail keeps counts sane

        const float* sA = smem + (kt % NS) * STAGE_WORDS;
        const float* sB = sA + SM_A_WORDS;

#pragma unroll
        for (int ks = 0; ks < 4; ks++) {            // 4 x k8 = K chunk 32
            float a[4][4];
            float b[4][2];
#pragma unroll
            for (int mi = 0; mi < 4; mi++) {
                const float* p = sA + (wm + mi * 16 + g) * PITCH + ks * 8 + c;
                a[mi][0] = p[0];
                a[mi][2] = p[4];
                a[mi][1] = p[8 * PITCH];
                a[mi][3] = p[8 * PITCH + 4];
            }
#pragma unroll
            for (int ni = 0; ni < 4; ni++) {
                const float* p = sB + (wn + ni * 8 + g) * PITCH + ks * 8 + c;
                b[ni][0] = p[0];
                b[ni][1] = p[4];
            }
#pragma unroll
            for (int mi = 0; mi < 4; mi++)
#pragma unroll
                for (int ni = 0; ni < 4; ni++)
                    mma8(acc[mi][ni], a[mi], b[ni]);
        }
    }

    // ---- epilogue: direct stores (float2 per fragment half) -----------------
#pragma unroll
    for (int mi = 0; mi < 4; mi++) {
        const int r0 = m0 + wm + mi * 16 + g;
        const int r1 = r0 + 8;
#pragma unroll
        for (int ni = 0; ni < 4; ni++) {
            const int cc = n0 + wn + ni * 8 + 2 * c;
            float2 v0 = make_float2(acc[mi][ni][0], acc[mi][ni][1]);
            float2 v1 = make_float2(acc[mi][ni][2], acc[mi][ni][3]);
            if (RELU_RNA) {
                v0.x = rna_tf32(fmaxf(v0.x, 0.0f));
                v0.y = rna_tf32(fmaxf(v0.y, 0.0f));
                v1.x = rna_tf32(fmaxf(v1.x, 0.0f));
                v1.y = rna_tf32(fmaxf(v1.y, 0.0f));
            }
            *(float2*)(Cg + (size_t)r0 * Nglob + cc) = v0;
            *(float2*)(Cg + (size_t)r1 * Nglob + cc) = v1;
        }
    }
}

// ---------------------------------------------------------------------------
// Weight merge: Wm = rna_tf32(W + 0.25 * B[a] @ A[a]),  W:[OUT,IN] row-major
// ---------------------------------------------------------------------------
__global__ void merge_w(const float* __restrict__ W, const float* __restrict__ A,
                        const float* __restrict__ Bm, const int* __restrict__ aid,
                        float* __restrict__ Wm, int OUT, int IN)
{
    const int in4 = IN >> 2;
    const int i = blockIdx.x * blockDim.x + threadIdx.x;
    if (i >= OUT * in4) return;
    const int f = i / in4;
    const int d = (i - f * in4) << 2;
    const int a = aid[0];

    const float* Aa = A + (size_t)a * RANKL * IN;
    const float* Ba = Bm + (size_t)a * OUT * RANKL + (size_t)f * RANKL;
    const float b0 = Ba[0] * 0.25f, b1 = Ba[1] * 0.25f,
                b2 = Ba[2] * 0.25f, b3 = Ba[3] * 0.25f;

    float4 w = ((const float4*)W)[i];
    const float4 a0 = *(const float4*)(Aa + 0 * (size_t)IN + d);
    const float4 a1 = *(const float4*)(Aa + 1 * (size_t)IN + d);
    const float4 a2 = *(const float4*)(Aa + 2 * (size_t)IN + d);
    const float4 a3 = *(const float4*)(Aa + 3 * (size_t)IN + d);

    w.x = rna_tf32(w.x + b0 * a0.x + b1 * a1.x + b2 * a2.x + b3 * a3.x);
    w.y = rna_tf32(w.y + b0 * a0.y + b1 * a1.y + b2 * a2.y + b3 * a3.y);
    w.z = rna_tf32(w.z + b0 * a0.z + b1 * a1.z + b2 * a2.z + b3 * a3.z);
    w.w = rna_tf32(w.w + b0 * a0.w + b1 * a1.w + b2 * a2.w + b3 * a3.w);
    ((float4*)Wm)[i] = w;
}

// ---------------------------------------------------------------------------
// Activation pre-round: xr = rna_tf32(x)
// ---------------------------------------------------------------------------
__global__ void rna_copy(const float4* __restrict__ in, float4* __restrict__ out,
                         int n4)
{
    const int i = blockIdx.x * blockDim.x + threadIdx.x;
    if (i >= n4) return;
    float4 v = in[i];
    v.x = rna_tf32(v.x); v.y = rna_tf32(v.y);
    v.z = rna_tf32(v.z); v.w = rna_tf32(v.w);
    out[i] = v;
}

// ---------------------------------------------------------------------------
// Launch
// ---------------------------------------------------------------------------
extern "C" void kernel_launch(void* const* d_in, const int* in_sizes, int n_in,
                              void* d_out, int out_size)
{
    const float* x   = (const float*)d_in[0];
    const float* W1  = (const float*)d_in[1];
    const float* A1  = (const float*)d_in[2];
    const float* B1  = (const float*)d_in[3];
    const float* W2  = (const float*)d_in[4];
    const float* A2  = (const float*)d_in[5];
    const float* B2  = (const float*)d_in[6];
    const int*   aid = (const int*)d_in[7];
    float* out = (float*)d_out;

    float *xr, *h, *w1, *w2;
    cudaGetSymbolAddress((void**)&xr, g_xr);
    cudaGetSymbolAddress((void**)&h,  g_h);
    cudaGetSymbolAddress((void**)&w1, g_w1);
    cudaGetSymbolAddress((void**)&w2, g_w2);

    cudaFuncSetAttribute(gemm_tf32<true>,
                         cudaFuncAttributeMaxDynamicSharedMemorySize, SMEM_TOTAL);
    cudaFuncSetAttribute(gemm_tf32<false>,
                         cudaFuncAttributeMaxDynamicSharedMemorySize, SMEM_TOTAL);

    // 1) round x to tf32 (rna)
    const int n4x = TOK * DMODEL / 4;
    rna_copy<<<(n4x + 255) / 256, 256>>>((const float4*)x, (float4*)xr, n4x);

    // 2) fold LoRA into weights + rna round
    const int n4w = DFF * DMODEL / 4;
    merge_w<<<(n4w + 255) / 256, 256>>>(W1, A1, B1, aid, w1, DFF, DMODEL);
    merge_w<<<(n4w + 255) / 256, 256>>>(W2, A2, B2, aid, w2, DMODEL, DFF);

    // 3) h = rna(relu(xr @ w1^T))      M=16384, N=4096, K=1024
    dim3 g1(DFF / TN, TOK / TM);
    gemm_tf32<true><<<g1, 256, SMEM_TOTAL>>>(xr, w1, h, DMODEL, DMODEL / TKC, DFF);

    // 4) out = h @ w2^T                M=16384, N=1024, K=4096
    dim3 g2(DMODEL / TN, TOK / TM);
    gemm_tf32<false><<<g2, 256, SMEM_TOTAL>>>(h, w2, out, DFF, DFF / TKC, DMODEL);
}

// round 7
// speedup vs baseline: 1.6687x; 1.0563x over previous
#include <cuda_runtime.h>
#include <cstdint>

// ============================================================================
// FeedForwardLoRA on GB300 (sm_103) — tf32 mma.sync path, R7.
// R6 @1638us: tensor stuck at 56.7% because the smem crossbar (LDS:mma = 1.5:1
// at 64x32 warp tiles, + cp.async stores) co-binds with the HMMA floor
// (2048 vs 2048 cyc/chunk/SM). R7: 4 warps of 64x64 per CTA (128 threads)
// restores LDS:mma = 1:1 -> crossbar 1536 cyc < tensor 2048 cyc, tensor
// becomes the sole binder. Still 2 CTAs/SM (smem 110.6KB, regs <=256).
//
//   W1e = rna_tf32(W1 + 0.25 * B1[a] @ A1[a])
//   W2e = rna_tf32(W2 + 0.25 * B2[a] @ A2[a])
//   xr  = rna_tf32(x)
//   h   = rna_tf32(relu(xr @ W1e^T))     GEMM1: M=16384 N=4096 K=1024
//   out = h @ W2e^T                      GEMM2: M=16384 N=1024 K=4096
// ============================================================================

#define TOK     16384
#define DMODEL  1024
#define DFF     4096
#define RANKL   4

#define TM   128          // CTA M tile
#define TN   128          // CTA N tile
#define TKC  32           // K chunk
#define NS   3            // cp.async pipeline stages
#define PITCH 36          // smem row pitch in floats (skew-4 -> conflict-free)

#define SM_A_WORDS (TM * PITCH)                 // 4608 floats
#define SM_B_WORDS (TN * PITCH)                 // 4608 floats
#define STAGE_WORDS (SM_A_WORDS + SM_B_WORDS)   // 9216 floats = 36864 B
#define SMEM_TOTAL (NS * STAGE_WORDS * 4)       // 110592 B  (x2 CTAs = 221184/SM)

// ---------------------------------------------------------------------------
// Scratch (static __device__ arrays — the sanctioned no-alloc workaround)
// ---------------------------------------------------------------------------
__device__ float g_xr[(size_t)TOK * DMODEL];    //  64 MB
__device__ float g_h [(size_t)TOK * DFF];       // 256 MB
__device__ float g_w1[(size_t)DFF * DMODEL];    //  16 MB
__device__ float g_w2[(size_t)DMODEL * DFF];    //  16 MB

// ---------------------------------------------------------------------------
// Helpers
// ---------------------------------------------------------------------------
__device__ __forceinline__ uint32_t smem_u32(const void* p) {
    uint32_t a;
    asm("{ .reg .u64 t; cvta.to.shared.u64 t, %1; cvt.u32.u64 %0, t; }"
        : "=r"(a) : "l"(p));
    return a;
}

__device__ __forceinline__ float rna_tf32(float v) {
    uint32_t o;
    asm("cvt.rna.tf32.f32 %0, %1;" : "=r"(o) : "f"(v));
    return __uint_as_float(o);
}

#define CPA16(smem_addr, gptr) \
    asm volatile("cp.async.cg.shared.global [%0], [%1], 16;" \
                 :: "r"(smem_addr), "l"(gptr))
#define CP_COMMIT()  asm volatile("cp.async.commit_group;" ::: "memory")
#define CP_WAIT_1()  asm volatile("cp.async.wait_group 1;" ::: "memory")   // NS-2

// D += A * B   (m16n8k8, tf32 inputs, fp32 accumulate)
__device__ __forceinline__ void mma8(float* d, const float* a, const float* b) {
    asm volatile(
        "mma.sync.aligned.m16n8k8.row.col.f32.tf32.tf32.f32 "
        "{%0,%1,%2,%3}, {%4,%5,%6,%7}, {%8,%9}, {%0,%1,%2,%3};"
        : "+f"(d[0]), "+f"(d[1]), "+f"(d[2]), "+f"(d[3])
        : "r"(__float_as_uint(a[0])), "r"(__float_as_uint(a[1])),
          "r"(__float_as_uint(a[2])), "r"(__float_as_uint(a[3])),
          "r"(__float_as_uint(b[0])), "r"(__float_as_uint(b[1])));
}

// ---------------------------------------------------------------------------
// GEMM: C[M, Nglob] = op(A[M,K] @ B[Nglob,K]^T).  op = relu+rna or identity.
// Grid (Nglob/TN, M/TM), 128 threads = 4 warps of 64x64 tiles (2 x 2 layout).
// 2 CTAs per SM. All dims divide exactly — no tails anywhere.
// ---------------------------------------------------------------------------
template <bool RELU_RNA>
__global__ void __launch_bounds__(128, 2)
gemm_tf32(const float* __restrict__ Ag, const float* __restrict__ Bg,
          float* __restrict__ Cg, int K, int KT, int Nglob)
{
    extern __shared__ float smem[];
    const uint32_t sbase = smem_u32(smem);
    const int tid = threadIdx.x;
    const int m0 = blockIdx.y * TM;
    const int n0 = blockIdx.x * TN;

    // ---- async-load geometry: thread -> (row, 16B chunk) --------------------
    const int lrow = tid >> 3;          // 0..15
    const int lchk = tid & 7;           // 0..7  (16B units across the 128B row)

    auto load_stage = [&](int slot, int kt) {
        const uint32_t sw = sbase + (uint32_t)(slot * STAGE_WORDS) * 4u;
        const size_t kofs = (size_t)kt * TKC + lchk * 4;
        const uint32_t cofs = (uint32_t)(lchk * 4) * 4u;
#pragma unroll
        for (int j = 0; j < 8; j++) {                       // A: 128 rows
            const int r = lrow + 16 * j;
            CPA16(sw + (uint32_t)(r * PITCH) * 4u + cofs,
                  Ag + (size_t)(m0 + r) * K + kofs);
        }
#pragma unroll
        for (int j = 0; j < 8; j++) {                       // B: 128 rows
            const int r = lrow + 16 * j;
            CPA16(sw + (uint32_t)(SM_A_WORDS + r * PITCH) * 4u + cofs,
                  Bg + (size_t)(n0 + r) * K + kofs);
        }
    };

    // ---- compute geometry ---------------------------------------------------
    const int lane = tid & 31;
    const int w = tid >> 5;             // 0..3
    const int wm = (w & 1) * 64;        // warp M offset within CTA tile
    const int wn = (w >> 1) * 64;       // warp N offset
    const int g = lane >> 2;            // fragment group (row within 8)
    const int c = lane & 3;             // fragment thread-in-group (k within 4)

    float acc[4][8][4];
#pragma unroll
    for (int mi = 0; mi < 4; mi++)
#pragma unroll
        for (int ni = 0; ni < 8; ni++)
#pragma unroll
            for (int q = 0; q < 4; q++) acc[mi][ni][q] = 0.0f;

    // ---- prologue: stages 0..NS-2 -------------------------------------------
#pragma unroll
    for (int s = 0; s < NS - 1; s++) {
        load_stage(s, s);
        CP_COMMIT();
    }

    // ---- main loop ----------------------------------------------------------
    for (int kt = 0; kt < KT; kt++) {
        CP_WAIT_1();                    // stage kt landed
        __syncthreads();                // visible to all; prior compute retired

        const int pf = kt + NS - 1;
        if (pf < KT) load_stage(pf % NS, pf);
        CP_COMMIT();                    // empty group on tail keeps counts sane

        const float* sA = smem + (kt % NS) * STAGE_WORDS;
        const float* sB = sA + SM_A_WORDS;

#pragma unroll
        for (int ks = 0; ks < 4; ks++) {            // 4 x k8 = K chunk 32
            float a[4][4];
            float b[8][2];
#pragma unroll
            for (int mi = 0; mi < 4; mi++) {
                const float* p = sA + (wm + mi * 16 + g) * PITCH + ks * 8 + c;
                a[mi][0] = p[0];
                a[mi][2] = p[4];
                a[mi][1] = p[8 * PITCH];
                a[mi][3] = p[8 * PITCH + 4];
            }
#pragma unroll
            for (int ni = 0; ni < 8; ni++) {
                const float* p = sB + (wn + ni * 8 + g) * PITCH + ks * 8 + c;
                b[ni][0] = p[0];
                b[ni][1] = p[4];
            }
#pragma unroll
            for (int mi = 0; mi < 4; mi++)
#pragma unroll
                for (int ni = 0; ni < 8; ni++)
                    mma8(acc[mi][ni], a[mi], b[ni]);
        }
    }

    // ---- epilogue: direct stores (float2 per fragment half) -----------------
#pragma unroll
    for (int mi = 0; mi < 4; mi++) {
        const int r0 = m0 + wm + mi * 16 + g;
        const int r1 = r0 + 8;
#pragma unroll
        for (int ni = 0; ni < 8; ni++) {
            const int cc = n0 + wn + ni * 8 + 2 * c;
            float2 v0 = make_float2(acc[mi][ni][0], acc[mi][ni][1]);
            float2 v1 = make_float2(acc[mi][ni][2], acc[mi][ni][3]);
            if (RELU_RNA) {
                v0.x = rna_tf32(fmaxf(v0.x, 0.0f));
                v0.y = rna_tf32(fmaxf(v0.y, 0.0f));
                v1.x = rna_tf32(fmaxf(v1.x, 0.0f));
                v1.y = rna_tf32(fmaxf(v1.y, 0.0f));
            }
            *(float2*)(Cg + (size_t)r0 * Nglob + cc) = v0;
            *(float2*)(Cg + (size_t)r1 * Nglob + cc) = v1;
        }
    }
}

// ---------------------------------------------------------------------------
// Weight merge: Wm = rna_tf32(W + 0.25 * B[a] @ A[a]),  W:[OUT,IN] row-major
// ---------------------------------------------------------------------------
__global__ void merge_w(const float* __restrict__ W, const float* __restrict__ A,
                        const float* __restrict__ Bm, const int* __restrict__ aid,
                        float* __restrict__ Wm, int OUT, int IN)
{
    const int in4 = IN >> 2;
    const int i = blockIdx.x * blockDim.x + threadIdx.x;
    if (i >= OUT * in4) return;
    const int f = i / in4;
    const int d = (i - f * in4) << 2;
    const int a = aid[0];

    const float* Aa = A + (size_t)a * RANKL * IN;
    const float* Ba = Bm + (size_t)a * OUT * RANKL + (size_t)f * RANKL;
    const float b0 = Ba[0] * 0.25f, b1 = Ba[1] * 0.25f,
                b2 = Ba[2] * 0.25f, b3 = Ba[3] * 0.25f;

    float4 w = ((const float4*)W)[i];
    const float4 a0 = *(const float4*)(Aa + 0 * (size_t)IN + d);
    const float4 a1 = *(const float4*)(Aa + 1 * (size_t)IN + d);
    const float4 a2 = *(const float4*)(Aa + 2 * (size_t)IN + d);
    const float4 a3 = *(const float4*)(Aa + 3 * (size_t)IN + d);

    w.x = rna_tf32(w.x + b0 * a0.x + b1 * a1.x + b2 * a2.x + b3 * a3.x);
    w.y = rna_tf32(w.y + b0 * a0.y + b1 * a1.y + b2 * a2.y + b3 * a3.y);
    w.z = rna_tf32(w.z + b0 * a0.z + b1 * a1.z + b2 * a2.z + b3 * a3.z);
    w.w = rna_tf32(w.w + b0 * a0.w + b1 * a1.w + b2 * a2.w + b3 * a3.w);
    ((float4*)Wm)[i] = w;
}

// ---------------------------------------------------------------------------
// Activation pre-round: xr = rna_tf32(x)
// ---------------------------------------------------------------------------
__global__ void rna_copy(const float4* __restrict__ in, float4* __restrict__ out,
                         int n4)
{
    const int i = blockIdx.x * blockDim.x + threadIdx.x;
    if (i >= n4) return;
    float4 v = in[i];
    v.x = rna_tf32(v.x); v.y = rna_tf32(v.y);
    v.z = rna_tf32(v.z); v.w = rna_tf32(v.w);
    out[i] = v;
}

// ---------------------------------------------------------------------------
// Launch
// ---------------------------------------------------------------------------
extern "C" void kernel_launch(void* const* d_in, const int* in_sizes, int n_in,
                              void* d_out, int out_size)
{
    const float* x   = (const float*)d_in[0];
    const float* W1  = (const float*)d_in[1];
    const float* A1  = (const float*)d_in[2];
    const float* B1  = (const float*)d_in[3];
    const float* W2  = (const float*)d_in[4];
    const float* A2  = (const float*)d_in[5];
    const float* B2  = (const float*)d_in[6];
    const int*   aid = (const int*)d_in[7];
    float* out = (float*)d_out;

    float *xr, *h, *w1, *w2;
    cudaGetSymbolAddress((void**)&xr, g_xr);
    cudaGetSymbolAddress((void**)&h,  g_h);
    cudaGetSymbolAddress((void**)&w1, g_w1);
    cudaGetSymbolAddress((void**)&w2, g_w2);

    cudaFuncSetAttribute(gemm_tf32<true>,
                         cudaFuncAttributeMaxDynamicSharedMemorySize, SMEM_TOTAL);
    cudaFuncSetAttribute(gemm_tf32<false>,
                         cudaFuncAttributeMaxDynamicSharedMemorySize, SMEM_TOTAL);

    // 1) round x to tf32 (rna)
    const int n4x = TOK * DMODEL / 4;
    rna_copy<<<(n4x + 255) / 256, 256>>>((const float4*)x, (float4*)xr, n4x);

    // 2) fold LoRA into weights + rna round
    const int n4w = DFF * DMODEL / 4;
    merge_w<<<(n4w + 255) / 256, 256>>>(W1, A1, B1, aid, w1, DFF, DMODEL);
    merge_w<<<(n4w + 255) / 256, 256>>>(W2, A2, B2, aid, w2, DMODEL, DFF);

    // 3) h = rna(relu(xr @ w1^T))      M=16384, N=4096, K=1024
    dim3 g1(DFF / TN, TOK / TM);
    gemm_tf32<true><<<g1, 128, SMEM_TOTAL>>>(xr, w1, h, DMODEL, DMODEL / TKC, DFF);

    // 4) out = h @ w2^T                M=16384, N=1024, K=4096
    dim3 g2(DMODEL / TN, TOK / TM);
    gemm_tf32<false><<<g2, 128, SMEM_TOTAL>>>(h, w2, out, DFF, DFF / TKC, DMODEL);
}

// round 10
// speedup vs baseline: 2.9712x; 1.7806x over previous
#include <cuda_runtime.h>
#include <cuda_fp16.h>
#include <cstdint>

// ============================================================================
// FeedForwardLoRA on GB300 (sm_103) — fp16 mma.sync path, R9 (= R8 resubmit;
// R8 hit a broker infra failure before any compile/run).
// R7 @1550us closed the model: tf32 mma.sync peaks at 512 MACs/cyc/SM (Ampere
// rate); we were at 60% of it. fp16 m16n8k16 has the same 11-bit mantissa as
// tf32 (same rel_err) but 2x the rate, half the traffic, and k64 chunks in the
// same smem budget (half the barriers). ldmatrix.x4 feeds fragments with 4x
// fewer shared-pipe instructions.
//
//   W1h = f16_rn(W1 + 0.25 * B1[a] @ A1[a])
//   W2h = f16_rn(W2 + 0.25 * B2[a] @ A2[a])
//   xh  = f16_rn(x)
//   h   = f16_rn(relu(xh @ W1h^T))       GEMM1: M=16384 N=4096 K=1024
//   out = h @ W2h^T  (fp32 out)          GEMM2: M=16384 N=1024 K=4096
// ============================================================================

#define TOK     16384
#define DMODEL  1024
#define DFF     4096
#define RANKL   4

#define TM   128          // CTA M tile
#define TN   128          // CTA N tile
#define TKC  64           // K chunk (halves) = 128B per row
#define NS   3            // cp.async pipeline stages
#define PITCHB 144        // smem row pitch in bytes (128B data + 16B skew)

#define SM_A_BYTES (TM * PITCHB)                // 18432 B
#define SM_B_BYTES (TN * PITCHB)                // 18432 B
#define STAGE_BYTES (SM_A_BYTES + SM_B_BYTES)   // 36864 B
#define SMEM_TOTAL (NS * STAGE_BYTES)           // 110592 B (x2 CTAs = 221184/SM)

// ---------------------------------------------------------------------------
// Scratch (static __device__ arrays — the sanctioned no-alloc workaround)
// ---------------------------------------------------------------------------
__device__ __half g_xh [(size_t)TOK * DMODEL];  //  32 MB
__device__ __half g_h  [(size_t)TOK * DFF];     // 128 MB
__device__ __half g_w1h[(size_t)DFF * DMODEL];  //   8 MB
__device__ __half g_w2h[(size_t)DMODEL * DFF];  //   8 MB

// ---------------------------------------------------------------------------
// Helpers
// ---------------------------------------------------------------------------
__device__ __forceinline__ uint32_t smem_u32(const void* p) {
    uint32_t a;
    asm("{ .reg .u64 t; cvta.to.shared.u64 t, %1; cvt.u32.u64 %0, t; }"
        : "=r"(a) : "l"(p));
    return a;
}

#define CPA16(smem_addr, gptr) \
    asm volatile("cp.async.cg.shared.global [%0], [%1], 16;" \
                 :: "r"(smem_addr), "l"(gptr))
#define CP_COMMIT()  asm volatile("cp.async.commit_group;" ::: "memory")
#define CP_WAIT_1()  asm volatile("cp.async.wait_group 1;" ::: "memory")   // NS-2

#define LDSM_X4(r0, r1, r2, r3, addr) \
    asm volatile("ldmatrix.sync.aligned.m8n8.x4.shared.b16 {%0,%1,%2,%3}, [%4];" \
                 : "=r"(r0), "=r"(r1), "=r"(r2), "=r"(r3) : "r"(addr))

// D += A * B   (m16n8k16, fp16 inputs, fp32 accumulate)
__device__ __forceinline__ void mma16(float* d, const uint32_t* a,
                                      uint32_t b0, uint32_t b1) {
    asm volatile(
        "mma.sync.aligned.m16n8k16.row.col.f32.f16.f16.f32 "
        "{%0,%1,%2,%3}, {%4,%5,%6,%7}, {%8,%9}, {%0,%1,%2,%3};"
        : "+f"(d[0]), "+f"(d[1]), "+f"(d[2]), "+f"(d[3])
        : "r"(a[0]), "r"(a[1]), "r"(a[2]), "r"(a[3]), "r"(b0), "r"(b1));
}

// ---------------------------------------------------------------------------
// GEMM: C[M, Nglob] = op(A[M,K] @ B[Nglob,K]^T), fp16 in, fp32 accumulate.
// STORE_HALF_RELU: C = f16_rn(relu(.)) as half.  Else: C = fp32.
// Grid (Nglob/TN, M/TM), 128 threads = 4 warps of 64x64 tiles (2x2 layout).
// 2 CTAs per SM. All dims divide exactly — no tails anywhere.
// ---------------------------------------------------------------------------
template <bool STORE_HALF_RELU>
__global__ void __launch_bounds__(128, 2)
gemm_f16(const __half* __restrict__ Ag, const __half* __restrict__ Bg,
         void* __restrict__ Cg_, int K, int KT, int Nglob)
{
    extern __shared__ char smem[];
    const uint32_t sbase = smem_u32(smem);
    const int tid = threadIdx.x;
    const int m0 = blockIdx.y * TM;
    const int n0 = blockIdx.x * TN;

    // ---- async-load geometry: thread -> (row, 16B chunk) --------------------
    const int lrow = tid >> 3;          // 0..15
    const int lchk = tid & 7;           // 0..7  (16B units across the 128B row)

    auto load_stage = [&](int slot, int kt) {
        const uint32_t sw = sbase + (uint32_t)slot * STAGE_BYTES;
        const size_t kofs = (size_t)kt * TKC + lchk * 8;    // halves
        const uint32_t cofs = (uint32_t)lchk * 16;          // bytes
#pragma unroll
        for (int j = 0; j < 8; j++) {                       // A: 128 rows
            const int r = lrow + 16 * j;
            CPA16(sw + (uint32_t)r * PITCHB + cofs,
                  Ag + (size_t)(m0 + r) * K + kofs);
        }
#pragma unroll
        for (int j = 0; j < 8; j++) {                       // B: 128 rows
            const int r = lrow + 16 * j;
            CPA16(sw + SM_A_BYTES + (uint32_t)r * PITCHB + cofs,
                  Bg + (size_t)(n0 + r) * K + kofs);
        }
    };

    // ---- compute geometry ---------------------------------------------------
    const int lane = tid & 31;
    const int w = tid >> 5;             // 0..3
    const int wm = (w & 1) * 64;        // warp M offset within CTA tile
    const int wn = (w >> 1) * 64;       // warp N offset
    const int g = lane >> 2;            // fragment group (row within 8)
    const int c = lane & 3;             // fragment thread-in-group

    // ldmatrix lane -> (matrix id, row-in-matrix)
    const int lsub = lane >> 3;         // 0..3
    const int lr8  = lane & 7;          // 0..7
    // matrix id mapping: lsub0:(+0 rows, k0-7) lsub1:(+8, k0-7)
    //                    lsub2:(+0, k8-15)     lsub3:(+8, k8-15)
    const uint32_t arow = (uint32_t)(wm + (lsub & 1) * 8 + lr8);
    const uint32_t brow = (uint32_t)(wn + (lsub & 1) * 8 + lr8);
    const uint32_t koff = (uint32_t)(lsub >> 1) * 16;       // bytes

    float acc[4][8][4];
#pragma unroll
    for (int mi = 0; mi < 4; mi++)
#pragma unroll
        for (int ni = 0; ni < 8; ni++)
#pragma unroll
            for (int q = 0; q < 4; q++) acc[mi][ni][q] = 0.0f;

    // ---- prologue: stages 0..NS-2 -------------------------------------------
#pragma unroll
    for (int s = 0; s < NS - 1; s++) {
        load_stage(s, s);
        CP_COMMIT();
    }

    // ---- main loop ----------------------------------------------------------
    for (int kt = 0; kt < KT; kt++) {
        CP_WAIT_1();                    // stage kt landed
        __syncthreads();                // visible to all; prior compute retired

        const int pf = kt + NS - 1;
        if (pf < KT) load_stage(pf % NS, pf);
        CP_COMMIT();                    // empty group on tail keeps counts sane

        const uint32_t sA = sbase + (uint32_t)(kt % NS) * STAGE_BYTES;
        const uint32_t aB = sA + arow * PITCHB + koff;
        const uint32_t bB = sA + SM_A_BYTES + brow * PITCHB + koff;

#pragma unroll
        for (int ks = 0; ks < 4; ks++) {            // 4 x k16 = K chunk 64
            uint32_t a[4][4];
            uint32_t b[4][4];
#pragma unroll
            for (int mi = 0; mi < 4; mi++)
                LDSM_X4(a[mi][0], a[mi][1], a[mi][2], a[mi][3],
                        aB + (uint32_t)mi * (16 * PITCHB) + (uint32_t)ks * 32);
#pragma unroll
            for (int pi = 0; pi < 4; pi++)
                LDSM_X4(b[pi][0], b[pi][1], b[pi][2], b[pi][3],
                        bB + (uint32_t)pi * (16 * PITCHB) + (uint32_t)ks * 32);
#pragma unroll
            for (int mi = 0; mi < 4; mi++)
#pragma unroll
                for (int ni = 0; ni < 8; ni++) {
                    const int pi = ni >> 1, o = ni & 1;
                    mma16(acc[mi][ni], a[mi], b[pi][o], b[pi][2 + o]);
                }
        }
    }

    // ---- epilogue -----------------------------------------------------------
#pragma unroll
    for (int mi = 0; mi < 4; mi++) {
        const int r0 = m0 + wm + mi * 16 + g;
        const int r1 = r0 + 8;
#pragma unroll
        for (int ni = 0; ni < 8; ni++) {
            const int cc = n0 + wn + ni * 8 + 2 * c;
            if (STORE_HALF_RELU) {
                __half* C = (__half*)Cg_;
                __half2 v0 = __floats2half2_rn(fmaxf(acc[mi][ni][0], 0.0f),
                                               fmaxf(acc[mi][ni][1], 0.0f));
                __half2 v1 = __floats2half2_rn(fmaxf(acc[mi][ni][2], 0.0f),
                                               fmaxf(acc[mi][ni][3], 0.0f));
                *(__half2*)(C + (size_t)r0 * Nglob + cc) = v0;
                *(__half2*)(C + (size_t)r1 * Nglob + cc) = v1;
            } else {
                float* C = (float*)Cg_;
                *(float2*)(C + (size_t)r0 * Nglob + cc) =
                    make_float2(acc[mi][ni][0], acc[mi][ni][1]);
                *(float2*)(C + (size_t)r1 * Nglob + cc) =
                    make_float2(acc[mi][ni][2], acc[mi][ni][3]);
            }
        }
    }
}

// ---------------------------------------------------------------------------
// Weight merge: Wm = f16_rn(W + 0.25 * B[a] @ A[a]),  W:[OUT,IN] row-major
// ---------------------------------------------------------------------------
__global__ void merge_w(const float* __restrict__ W, const float* __restrict__ A,
                        const float* __restrict__ Bm, const int* __restrict__ aid,
                        __half* __restrict__ Wm, int OUT, int IN)
{
    const int in4 = IN >> 2;
    const int i = blockIdx.x * blockDim.x + threadIdx.x;
    if (i >= OUT * in4) return;
    const int f = i / in4;
    const int d = (i - f * in4) << 2;
    const int a = aid[0];

    const float* Aa = A + (size_t)a * RANKL * IN;
    const float* Ba = Bm + (size_t)a * OUT * RANKL + (size_t)f * RANKL;
    const float b0 = Ba[0] * 0.25f, b1 = Ba[1] * 0.25f,
                b2 = Ba[2] * 0.25f, b3 = Ba[3] * 0.25f;

    float4 w = ((const float4*)W)[i];
    const float4 a0 = *(const float4*)(Aa + 0 * (size_t)IN + d);
    const float4 a1 = *(const float4*)(Aa + 1 * (size_t)IN + d);
    const float4 a2 = *(const float4*)(Aa + 2 * (size_t)IN + d);
    const float4 a3 = *(const float4*)(Aa + 3 * (size_t)IN + d);

    __half2 lo = __floats2half2_rn(w.x + b0 * a0.x + b1 * a1.x + b2 * a2.x + b3 * a3.x,
                                   w.y + b0 * a0.y + b1 * a1.y + b2 * a2.y + b3 * a3.y);
    __half2 hi = __floats2half2_rn(w.z + b0 * a0.z + b1 * a1.z + b2 * a2.z + b3 * a3.z,
                                   w.w + b0 * a0.w + b1 * a1.w + b2 * a2.w + b3 * a3.w);
    __half2* dst = (__half2*)(Wm + (size_t)i * 4);
    dst[0] = lo;
    dst[1] = hi;
}

// ---------------------------------------------------------------------------
// Activation pre-round: xh = f16_rn(x)
// ---------------------------------------------------------------------------
__global__ void to_half(const float4* __restrict__ in, __half* __restrict__ out,
                        int n4)
{
    const int i = blockIdx.x * blockDim.x + threadIdx.x;
    if (i >= n4) return;
    float4 v = in[i];
    __half2* dst = (__half2*)(out + (size_t)i * 4);
    dst[0] = __floats2half2_rn(v.x, v.y);
    dst[1] = __floats2half2_rn(v.z, v.w);
}

// ---------------------------------------------------------------------------
// Launch
// ---------------------------------------------------------------------------
extern "C" void kernel_launch(void* const* d_in, const int* in_sizes, int n_in,
                              void* d_out, int out_size)
{
    const float* x   = (const float*)d_in[0];
    const float* W1  = (const float*)d_in[1];
    const float* A1  = (const float*)d_in[2];
    const float* B1  = (const float*)d_in[3];
    const float* W2  = (const float*)d_in[4];
    const float* A2  = (const float*)d_in[5];
    const float* B2  = (const float*)d_in[6];
    const int*   aid = (const int*)d_in[7];
    float* out = (float*)d_out;

    __half *xh, *h, *w1h, *w2h;
    cudaGetSymbolAddress((void**)&xh,  g_xh);
    cudaGetSymbolAddress((void**)&h,   g_h);
    cudaGetSymbolAddress((void**)&w1h, g_w1h);
    cudaGetSymbolAddress((void**)&w2h, g_w2h);

    cudaFuncSetAttribute(gemm_f16<true>,
                         cudaFuncAttributeMaxDynamicSharedMemorySize, SMEM_TOTAL);
    cudaFuncSetAttribute(gemm_f16<false>,
                         cudaFuncAttributeMaxDynamicSharedMemorySize, SMEM_TOTAL);

    // 1) x -> fp16
    const int n4x = TOK * DMODEL / 4;
    to_half<<<(n4x + 255) / 256, 256>>>((const float4*)x, xh, n4x);

    // 2) fold LoRA into weights, round to fp16
    const int n4w = DFF * DMODEL / 4;
    merge_w<<<(n4w + 255) / 256, 256>>>(W1, A1, B1, aid, w1h, DFF, DMODEL);
    merge_w<<<(n4w + 255) / 256, 256>>>(W2, A2, B2, aid, w2h, DMODEL, DFF);

    // 3) h = f16(relu(xh @ w1h^T))     M=16384, N=4096, K=1024
    dim3 g1(DFF / TN, TOK / TM);
    gemm_f16<true><<<g1, 128, SMEM_TOTAL>>>(xh, w1h, (void*)h,
                                            DMODEL, DMODEL / TKC, DFF);

    // 4) out = h @ w2h^T  (fp32)       M=16384, N=1024, K=4096
    dim3 g2(DMODEL / TN, TOK / TM);
    gemm_f16<false><<<g2, 128, SMEM_TOTAL>>>(h, w2h, (void*)out,
                                             DFF, DFF / TKC, DMODEL);
}

// round 11
// speedup vs baseline: 3.5282x; 1.1875x over previous
#include <cuda_runtime.h>
#include <cuda_fp16.h>
#include <cstdint>

// ============================================================================
// FeedForwardLoRA on GB300 (sm_103) — fp16 mma.sync path, R11.
// R10 @871us: tensor=53.8%. Mechanism found: every LDSM/mma is asm volatile,
// so the [ldsm burst][mma burst] source order per k-step is preserved exactly;
// crossbar phases (1536cyc) and tensor phases (2048cyc) serialize -> 3820cyc
// chunks. R11: manual register double-buffering of fragments (ldsm for ks+1
// hand-interleaved into ks's mma stream), cp.async stage load spread across
// the 4 k-steps, and compile-time K/N for cheap addressing.
//
//   W1h = f16_rn(W1 + 0.25 * B1[a] @ A1[a])
//   W2h = f16_rn(W2 + 0.25 * B2[a] @ A2[a])
//   xh  = f16_rn(x)
//   h   = f16_rn(relu(xh @ W1h^T))       GEMM1: M=16384 N=4096 K=1024
//   out = h @ W2h^T  (fp32 out)          GEMM2: M=16384 N=1024 K=4096
// ============================================================================

#define TOK     16384
#define DMODEL  1024
#define DFF     4096
#define RANKL   4

#define TM   128          // CTA M tile
#define TN   128          // CTA N tile
#define TKC  64           // K chunk (halves) = 128B per row
#define NS   3            // cp.async pipeline stages
#define PITCHB 144        // smem row pitch in bytes (128B data + 16B skew)

#define SM_A_BYTES (TM * PITCHB)                // 18432 B
#define SM_B_BYTES (TN * PITCHB)                // 18432 B
#define STAGE_BYTES (SM_A_BYTES + SM_B_BYTES)   // 36864 B
#define SMEM_TOTAL (NS * STAGE_BYTES)           // 110592 B (x2 CTAs = 221184/SM)

// ---------------------------------------------------------------------------
// Scratch (static __device__ arrays — the sanctioned no-alloc workaround)
// ---------------------------------------------------------------------------
__device__ __half g_xh [(size_t)TOK * DMODEL];  //  32 MB
__device__ __half g_h  [(size_t)TOK * DFF];     // 128 MB
__device__ __half g_w1h[(size_t)DFF * DMODEL];  //   8 MB
__device__ __half g_w2h[(size_t)DMODEL * DFF];  //   8 MB

// ---------------------------------------------------------------------------
// Helpers
// ---------------------------------------------------------------------------
__device__ __forceinline__ uint32_t smem_u32(const void* p) {
    uint32_t a;
    asm("{ .reg .u64 t; cvta.to.shared.u64 t, %1; cvt.u32.u64 %0, t; }"
        : "=r"(a) : "l"(p));
    return a;
}

#define CPA16(smem_addr, gptr) \
    asm volatile("cp.async.cg.shared.global [%0], [%1], 16;" \
                 :: "r"(smem_addr), "l"(gptr))
#define CP_COMMIT()  asm volatile("cp.async.commit_group;" ::: "memory")
#define CP_WAIT_1()  asm volatile("cp.async.wait_group 1;" ::: "memory")

#define LDSM_X4(r0, r1, r2, r3, addr) \
    asm volatile("ldmatrix.sync.aligned.m8n8.x4.shared.b16 {%0,%1,%2,%3}, [%4];" \
                 : "=r"(r0), "=r"(r1), "=r"(r2), "=r"(r3) : "r"(addr))

// D += A * B   (m16n8k16, fp16 inputs, fp32 accumulate)
__device__ __forceinline__ void mma16(float* d, const uint32_t* a,
                                      uint32_t b0, uint32_t b1) {
    asm volatile(
        "mma.sync.aligned.m16n8k16.row.col.f32.f16.f16.f32 "
        "{%0,%1,%2,%3}, {%4,%5,%6,%7}, {%8,%9}, {%0,%1,%2,%3};"
        : "+f"(d[0]), "+f"(d[1]), "+f"(d[2]), "+f"(d[3])
        : "r"(a[0]), "r"(a[1]), "r"(a[2]), "r"(a[3]), "r"(b0), "r"(b1));
}

// ---------------------------------------------------------------------------
// GEMM: C[M, NGLOB] = op(A[M,KDIM] @ B[NGLOB,KDIM]^T), fp16 in, fp32 acc.
// STORE_HALF_RELU: C = f16_rn(relu(.)) as half.  Else: C = fp32.
// Grid (NGLOB/TN, M/TM), 128 threads = 4 warps of 64x64 tiles (2x2 layout).
// 2 CTAs per SM. All dims divide exactly — no tails anywhere.
// ---------------------------------------------------------------------------
template <bool STORE_HALF_RELU, int KDIM, int NGLOB>
__global__ void __launch_bounds__(128, 2)
gemm_f16(const __half* __restrict__ Ag, const __half* __restrict__ Bg,
         void* __restrict__ Cg_)
{
    constexpr int KT = KDIM / TKC;
    extern __shared__ char smem[];
    const uint32_t sbase = smem_u32(smem);
    const int tid = threadIdx.x;
    const int m0 = blockIdx.y * TM;
    const int n0 = blockIdx.x * TN;

    // ---- async-load geometry: thread -> (row, 16B chunk) --------------------
    const int lrow = tid >> 3;          // 0..15
    const int lchk = tid & 7;           // 0..7  (16B units across the 128B row)

    // Quarter q loads rows j = 2q, 2q+1 of both tiles (4 CPA16 per thread).
    auto load_quarter = [&](int slot, int kt, int q) {
        const uint32_t sw = sbase + (uint32_t)slot * STAGE_BYTES;
        const size_t kofs = (size_t)kt * TKC + lchk * 8;    // halves
        const uint32_t cofs = (uint32_t)lchk * 16;          // bytes
#pragma unroll
        for (int j = 2 * q; j < 2 * q + 2; j++) {
            const int r = lrow + 16 * j;
            CPA16(sw + (uint32_t)r * PITCHB + cofs,
                  Ag + (size_t)(m0 + r) * KDIM + kofs);
            CPA16(sw + SM_A_BYTES + (uint32_t)r * PITCHB + cofs,
                  Bg + (size_t)(n0 + r) * KDIM + kofs);
        }
    };

    // ---- compute geometry ---------------------------------------------------
    const int lane = tid & 31;
    const int w = tid >> 5;             // 0..3
    const int wm = (w & 1) * 64;        // warp M offset within CTA tile
    const int wn = (w >> 1) * 64;       // warp N offset
    const int g = lane >> 2;            // fragment group (row within 8)
    const int c = lane & 3;             // fragment thread-in-group

    // ldmatrix lane -> (matrix id, row-in-matrix)
    const int lsub = lane >> 3;         // 0..3
    const int lr8  = lane & 7;          // 0..7
    const uint32_t arow = (uint32_t)(wm + (lsub & 1) * 8 + lr8);
    const uint32_t brow = (uint32_t)(wn + (lsub & 1) * 8 + lr8);
    const uint32_t koff = (uint32_t)(lsub >> 1) * 16;       // bytes

    float acc[4][8][4];
#pragma unroll
    for (int mi = 0; mi < 4; mi++)
#pragma unroll
        for (int ni = 0; ni < 8; ni++)
#pragma unroll
            for (int q = 0; q < 4; q++) acc[mi][ni][q] = 0.0f;

    // ---- prologue: stages 0..NS-2 -------------------------------------------
#pragma unroll
    for (int s = 0; s < NS - 1; s++) {
#pragma unroll
        for (int q = 0; q < 4; q++) load_quarter(s, s, q);
        CP_COMMIT();
    }

    // ---- main loop ----------------------------------------------------------
    for (int kt = 0; kt < KT; kt++) {
        CP_WAIT_1();                    // stage kt landed (commit-at-end scheme)
        __syncthreads();                // all writers done; slot reuse safe

        const int slot = kt % NS;
        const int pslot = (kt + 2) % NS;
        const bool do_pf = (kt + 2) < KT;
        const uint32_t sA = sbase + (uint32_t)slot * STAGE_BYTES;
        const uint32_t aB = sA + arow * PITCHB + koff;
        const uint32_t bB = sA + SM_A_BYTES + brow * PITCHB + koff;

        // Double-buffered fragments: preload ks=0, then during ks's mma
        // stream interleave the ldsm for ks+1 (volatile asm keeps this order).
        uint32_t af[2][4][4];
        uint32_t bf[2][4][4];
#pragma unroll
        for (int mi = 0; mi < 4; mi++) {
            LDSM_X4(af[0][mi][0], af[0][mi][1], af[0][mi][2], af[0][mi][3],
                    aB + (uint32_t)mi * (16 * PITCHB));
            LDSM_X4(bf[0][mi][0], bf[0][mi][1], bf[0][mi][2], bf[0][mi][3],
                    bB + (uint32_t)mi * (16 * PITCHB));
        }

#pragma unroll
        for (int ks = 0; ks < 4; ks++) {            // 4 x k16 = K chunk 64
            const int cur = ks & 1, nx = cur ^ 1;
            if (do_pf) load_quarter(pslot, kt + 2, ks);   // spread LDGSTS
#pragma unroll
            for (int mi = 0; mi < 4; mi++) {
                if (ks < 3) {
                    LDSM_X4(af[nx][mi][0], af[nx][mi][1],
                            af[nx][mi][2], af[nx][mi][3],
                            aB + (uint32_t)mi * (16 * PITCHB)
                               + (uint32_t)(ks + 1) * 32);
                    LDSM_X4(bf[nx][mi][0], bf[nx][mi][1],
                            bf[nx][mi][2], bf[nx][mi][3],
                            bB + (uint32_t)mi * (16 * PITCHB)
                               + (uint32_t)(ks + 1) * 32);
                }
#pragma unroll
                for (int ni = 0; ni < 8; ni++) {
                    const int pi = ni >> 1, o = ni & 1;
                    mma16(acc[mi][ni], af[cur][mi],
                          bf[cur][pi][o], bf[cur][pi][2 + o]);
                }
            }
        }
        CP_COMMIT();                    // one group per iteration (maybe empty)
    }

    // ---- epilogue -----------------------------------------------------------
#pragma unroll
    for (int mi = 0; mi < 4; mi++) {
        const int r0 = m0 + wm + mi * 16 + g;
        const int r1 = r0 + 8;
#pragma unroll
        for (int ni = 0; ni < 8; ni++) {
            const int cc = n0 + wn + ni * 8 + 2 * c;
            if (STORE_HALF_RELU) {
                __half* C = (__half*)Cg_;
                __half2 v0 = __floats2half2_rn(fmaxf(acc[mi][ni][0], 0.0f),
                                               fmaxf(acc[mi][ni][1], 0.0f));
                __half2 v1 = __floats2half2_rn(fmaxf(acc[mi][ni][2], 0.0f),
                                               fmaxf(acc[mi][ni][3], 0.0f));
                *(__half2*)(C + (size_t)r0 * NGLOB + cc) = v0;
                *(__half2*)(C + (size_t)r1 * NGLOB + cc) = v1;
            } else {
                float* C = (float*)Cg_;
                *(float2*)(C + (size_t)r0 * NGLOB + cc) =
                    make_float2(acc[mi][ni][0], acc[mi][ni][1]);
                *(float2*)(C + (size_t)r1 * NGLOB + cc) =
                    make_float2(acc[mi][ni][2], acc[mi][ni][3]);
            }
        }
    }
}

// ---------------------------------------------------------------------------
// Weight merge: Wm = f16_rn(W + 0.25 * B[a] @ A[a]),  W:[OUT,IN] row-major
// ---------------------------------------------------------------------------
__global__ void merge_w(const float* __restrict__ W, const float* __restrict__ A,
                        const float* __restrict__ Bm, const int* __restrict__ aid,
                        __half* __restrict__ Wm, int OUT, int IN)
{
    const int in4 = IN >> 2;
    const int i = blockIdx.x * blockDim.x + threadIdx.x;
    if (i >= OUT * in4) return;
    const int f = i / in4;
    const int d = (i - f * in4) << 2;
    const int a = aid[0];

    const float* Aa = A + (size_t)a * RANKL * IN;
    const float* Ba = Bm + (size_t)a * OUT * RANKL + (size_t)f * RANKL;
    const float b0 = Ba[0] * 0.25f, b1 = Ba[1] * 0.25f,
                b2 = Ba[2] * 0.25f, b3 = Ba[3] * 0.25f;

    float4 w = ((const float4*)W)[i];
    const float4 a0 = *(const float4*)(Aa + 0 * (size_t)IN + d);
    const float4 a1 = *(const float4*)(Aa + 1 * (size_t)IN + d);
    const float4 a2 = *(const float4*)(Aa + 2 * (size_t)IN + d);
    const float4 a3 = *(const float4*)(Aa + 3 * (size_t)IN + d);

    __half2 lo = __floats2half2_rn(w.x + b0 * a0.x + b1 * a1.x + b2 * a2.x + b3 * a3.x,
                                   w.y + b0 * a0.y + b1 * a1.y + b2 * a2.y + b3 * a3.y);
    __half2 hi = __floats2half2_rn(w.z + b0 * a0.z + b1 * a1.z + b2 * a2.z + b3 * a3.z,
                                   w.w + b0 * a0.w + b1 * a1.w + b2 * a2.w + b3 * a3.w);
    __half2* dst = (__half2*)(Wm + (size_t)i * 4);
    dst[0] = lo;
    dst[1] = hi;
}

// ---------------------------------------------------------------------------
// Activation pre-round: xh = f16_rn(x)
// ---------------------------------------------------------------------------
__global__ void to_half(const float4* __restrict__ in, __half* __restrict__ out,
                        int n4)
{
    const int i = blockIdx.x * blockDim.x + threadIdx.x;
    if (i >= n4) return;
    float4 v = in[i];
    __half2* dst = (__half2*)(out + (size_t)i * 4);
    dst[0] = __floats2half2_rn(v.x, v.y);
    dst[1] = __floats2half2_rn(v.z, v.w);
}

// ---------------------------------------------------------------------------
// Launch
// ---------------------------------------------------------------------------
extern "C" void kernel_launch(void* const* d_in, const int* in_sizes, int n_in,
                              void* d_out, int out_size)
{
    const float* x   = (const float*)d_in[0];
    const float* W1  = (const float*)d_in[1];
    const float* A1  = (const float*)d_in[2];
    const float* B1  = (const float*)d_in[3];
    const float* W2  = (const float*)d_in[4];
    const float* A2  = (const float*)d_in[5];
    const float* B2  = (const float*)d_in[6];
    const int*   aid = (const int*)d_in[7];
    float* out = (float*)d_out;

    __half *xh, *h, *w1h, *w2h;
    cudaGetSymbolAddress((void**)&xh,  g_xh);
    cudaGetSymbolAddress((void**)&h,   g_h);
    cudaGetSymbolAddress((void**)&w1h, g_w1h);
    cudaGetSymbolAddress((void**)&w2h, g_w2h);

    cudaFuncSetAttribute((gemm_f16<true, DMODEL, DFF>),
                         cudaFuncAttributeMaxDynamicSharedMemorySize, SMEM_TOTAL);
    cudaFuncSetAttribute((gemm_f16<false, DFF, DMODEL>),
                         cudaFuncAttributeMaxDynamicSharedMemorySize, SMEM_TOTAL);

    // 1) x -> fp16
    const int n4x = TOK * DMODEL / 4;
    to_half<<<(n4x + 255) / 256, 256>>>((const float4*)x, xh, n4x);

    // 2) fold LoRA into weights, round to fp16
    const int n4w = DFF * DMODEL / 4;
    merge_w<<<(n4w + 255) / 256, 256>>>(W1, A1, B1, aid, w1h, DFF, DMODEL);
    merge_w<<<(n4w + 255) / 256, 256>>>(W2, A2, B2, aid, w2h, DMODEL, DFF);

    // 3) h = f16(relu(xh @ w1h^T))     M=16384, N=4096, K=1024
    dim3 g1(DFF / TN, TOK / TM);
    gemm_f16<true, DMODEL, DFF><<<g1, 128, SMEM_TOTAL>>>(xh, w1h, (void*)h);

    // 4) out = h @ w2h^T  (fp32)       M=16384, N=1024, K=4096
    dim3 g2(DMODEL / TN, TOK / TM);
    gemm_f16<false, DFF, DMODEL><<<g2, 128, SMEM_TOTAL>>>(h, w2h, (void*)out);
}

// round 12
// speedup vs baseline: 3.6587x; 1.0370x over previous
#include <cuda_runtime.h>
#include <cuda_fp16.h>
#include <cstdint>

// ============================================================================
// FeedForwardLoRA on GB300 (sm_103) — fp16 mma.sync path, R12.
// R11 @733us, tensor=63.8%, fma=17.9%. Residual gap: (a) 8-ldsm preload burst
// at each chunk top before any mma can issue, (b) per-quarter 64-bit IMAD
// address rebuilds contending on the fma pipe. R12: uniform JIT pipeline —
// 16 groups/chunk of [8 mma + 2 ldsm], 5-ldsm preload, single-rotating A
// fragments; all gmem/smem addressing hoisted to advancing base pointers with
// compile-time offsets (KDIM/NGLOB template constants).
//
//   W1h = f16_rn(W1 + 0.25 * B1[a] @ A1[a])
//   W2h = f16_rn(W2 + 0.25 * B2[a] @ A2[a])
//   xh  = f16_rn(x)
//   h   = f16_rn(relu(xh @ W1h^T))       GEMM1: M=16384 N=4096 K=1024
//   out = h @ W2h^T  (fp32 out)          GEMM2: M=16384 N=1024 K=4096
// ============================================================================

#define TOK     16384
#define DMODEL  1024
#define DFF     4096
#define RANKL   4

#define TM   128          // CTA M tile
#define TN   128          // CTA N tile
#define TKC  64           // K chunk (halves) = 128B per row
#define NS   3            // cp.async pipeline stages
#define PITCHB 144        // smem row pitch in bytes (128B data + 16B skew)

#define SM_A_BYTES (TM * PITCHB)                // 18432 B
#define SM_B_BYTES (TN * PITCHB)                // 18432 B
#define STAGE_BYTES (SM_A_BYTES + SM_B_BYTES)   // 36864 B
#define SMEM_TOTAL (NS * STAGE_BYTES)           // 110592 B (x2 CTAs = 221184/SM)

// ---------------------------------------------------------------------------
// Scratch (static __device__ arrays — the sanctioned no-alloc workaround)
// ---------------------------------------------------------------------------
__device__ __half g_xh [(size_t)TOK * DMODEL];  //  32 MB
__device__ __half g_h  [(size_t)TOK * DFF];     // 128 MB
__device__ __half g_w1h[(size_t)DFF * DMODEL];  //   8 MB
__device__ __half g_w2h[(size_t)DMODEL * DFF];  //   8 MB

// ---------------------------------------------------------------------------
// Helpers
// ---------------------------------------------------------------------------
__device__ __forceinline__ uint32_t smem_u32(const void* p) {
    uint32_t a;
    asm("{ .reg .u64 t; cvta.to.shared.u64 t, %1; cvt.u32.u64 %0, t; }"
        : "=r"(a) : "l"(p));
    return a;
}

#define CPA16(smem_addr, gptr) \
    asm volatile("cp.async.cg.shared.global [%0], [%1], 16;" \
                 :: "r"(smem_addr), "l"(gptr))
#define CP_COMMIT()  asm volatile("cp.async.commit_group;" ::: "memory")
#define CP_WAIT_1()  asm volatile("cp.async.wait_group 1;" ::: "memory")

#define LDSM_X4(r0, r1, r2, r3, addr) \
    asm volatile("ldmatrix.sync.aligned.m8n8.x4.shared.b16 {%0,%1,%2,%3}, [%4];" \
                 : "=r"(r0), "=r"(r1), "=r"(r2), "=r"(r3) : "r"(addr))

// D += A * B   (m16n8k16, fp16 inputs, fp32 accumulate)
__device__ __forceinline__ void mma16(float* d, const uint32_t* a,
                                      uint32_t b0, uint32_t b1) {
    asm volatile(
        "mma.sync.aligned.m16n8k16.row.col.f32.f16.f16.f32 "
        "{%0,%1,%2,%3}, {%4,%5,%6,%7}, {%8,%9}, {%0,%1,%2,%3};"
        : "+f"(d[0]), "+f"(d[1]), "+f"(d[2]), "+f"(d[3])
        : "r"(a[0]), "r"(a[1]), "r"(a[2]), "r"(a[3]), "r"(b0), "r"(b1));
}

// ---------------------------------------------------------------------------
// GEMM: C[M, NGLOB] = op(A[M,KDIM] @ B[NGLOB,KDIM]^T), fp16 in, fp32 acc.
// STORE_HALF_RELU: C = f16_rn(relu(.)) as half.  Else: C = fp32.
// Grid (NGLOB/TN, M/TM), 128 threads = 4 warps of 64x64 tiles (2x2 layout).
// 2 CTAs per SM. All dims divide exactly — no tails anywhere.
// ---------------------------------------------------------------------------
template <bool STORE_HALF_RELU, int KDIM, int NGLOB>
__global__ void __launch_bounds__(128, 2)
gemm_f16(const __half* __restrict__ Ag, const __half* __restrict__ Bg,
         void* __restrict__ Cg_)
{
    constexpr int KT = KDIM / TKC;
    extern __shared__ char smem[];
    const uint32_t sbase = smem_u32(smem);
    const int tid = threadIdx.x;
    const int m0 = blockIdx.y * TM;
    const int n0 = blockIdx.x * TN;

    // ---- async-load geometry: thread -> (row, 16B chunk) --------------------
    const int lrow = tid >> 3;          // 0..15
    const int lchk = tid & 7;           // 0..7

    // Advancing gmem base pointers (row/lane parts fold to constants).
    const __half* agp = Ag + (size_t)(m0 + lrow) * KDIM + lchk * 8;
    const __half* bgp = Bg + (size_t)(n0 + lrow) * KDIM + lchk * 8;
    // Smem write base (slot-relative part added per chunk).
    const uint32_t swr = (uint32_t)lrow * PITCHB + (uint32_t)lchk * 16;

    // ---- compute geometry ---------------------------------------------------
    const int lane = tid & 31;
    const int w = tid >> 5;             // 0..3
    const int wm = (w & 1) * 64;        // warp M offset within CTA tile
    const int wn = (w >> 1) * 64;       // warp N offset
    const int g = lane >> 2;
    const int c = lane & 3;

    // ldmatrix lane -> (matrix id, row-in-matrix)
    const int lsub = lane >> 3;
    const int lr8  = lane & 7;
    const uint32_t arow = (uint32_t)(wm + (lsub & 1) * 8 + lr8);
    const uint32_t brow = (uint32_t)(wn + (lsub & 1) * 8 + lr8);
    const uint32_t koff = (uint32_t)(lsub >> 1) * 16;
    const uint32_t aoff = arow * PITCHB + koff;               // within stage
    const uint32_t boff = SM_A_BYTES + brow * PITCHB + koff;

    float acc[4][8][4];
#pragma unroll
    for (int mi = 0; mi < 4; mi++)
#pragma unroll
        for (int ni = 0; ni < 8; ni++)
#pragma unroll
            for (int q = 0; q < 4; q++) acc[mi][ni][q] = 0.0f;

    // ---- prologue: stages 0..NS-2 -------------------------------------------
#pragma unroll
    for (int s = 0; s < NS - 1; s++) {
        const uint32_t sw = sbase + (uint32_t)s * STAGE_BYTES + swr;
        const __half* ap = agp + s * TKC;
        const __half* bp = bgp + s * TKC;
#pragma unroll
        for (int j = 0; j < 8; j++) {
            CPA16(sw + (uint32_t)j * (16 * PITCHB), ap + (size_t)(16 * j) * KDIM);
            CPA16(sw + SM_A_BYTES + (uint32_t)j * (16 * PITCHB),
                  bp + (size_t)(16 * j) * KDIM);
        }
        CP_COMMIT();
    }
    agp += 2 * TKC;                     // prefetch cursor: stage kt+2
    bgp += 2 * TKC;

    // ---- main loop ----------------------------------------------------------
    int slot = 0, pslot = 2;
    for (int kt = 0; kt < KT; kt++) {
        CP_WAIT_1();                    // stage kt landed
        __syncthreads();                // all readers of slot pslot are done

        const bool do_pf = (kt + 2) < KT;
        const uint32_t sA = sbase + (uint32_t)slot * STAGE_BYTES;
        const uint32_t aB = sA + aoff;
        const uint32_t bB = sA + boff;
        const uint32_t swp = sbase + (uint32_t)pslot * STAGE_BYTES + swr;

        // Fragments: B double-buffered across ks (2x4x4); A rotates per group.
        uint32_t bf[2][4][4];
        uint32_t af[2][4];

        // Preload: bf[0][0..3] + af[group 0]  (5 ldsm)
#pragma unroll
        for (int pi = 0; pi < 4; pi++)
            LDSM_X4(bf[0][pi][0], bf[0][pi][1], bf[0][pi][2], bf[0][pi][3],
                    bB + (uint32_t)pi * (16 * PITCHB));
        LDSM_X4(af[0][0], af[0][1], af[0][2], af[0][3], aB);

#pragma unroll
        for (int ks = 0; ks < 4; ks++) {            // 4 x k16 = K chunk 64
            const int cur = ks & 1, nxt = cur ^ 1;
            // Spread prefetch: quarter ks of stage kt+2 (4 cp.async)
            if (do_pf) {
#pragma unroll
                for (int j = 2 * ks; j < 2 * ks + 2; j++) {
                    CPA16(swp + (uint32_t)j * (16 * PITCHB),
                          agp + (size_t)(16 * j) * KDIM);
                    CPA16(swp + SM_A_BYTES + (uint32_t)j * (16 * PITCHB),
                          bgp + (size_t)(16 * j) * KDIM);
                }
            }
#pragma unroll
            for (int mi = 0; mi < 4; mi++) {
                const int gidx = ks * 4 + mi;
                const int ap = gidx & 1, an = ap ^ 1;   // af parity
                // next group's A fragment (JIT, ~6 mma ahead of use)
                const int ng = gidx + 1;
                mma16(acc[mi][0], af[ap], bf[cur][0][0], bf[cur][0][2]);
                mma16(acc[mi][1], af[ap], bf[cur][0][1], bf[cur][0][3]);
                if (ng < 16)
                    LDSM_X4(af[an][0], af[an][1], af[an][2], af[an][3],
                            aB + (uint32_t)(ng & 3) * (16 * PITCHB)
                               + (uint32_t)(ng >> 2) * 32);
                mma16(acc[mi][2], af[ap], bf[cur][1][0], bf[cur][1][2]);
                mma16(acc[mi][3], af[ap], bf[cur][1][1], bf[cur][1][3]);
                if (ks < 3)             // B fragment pi=mi for ks+1 (JIT)
                    LDSM_X4(bf[nxt][mi][0], bf[nxt][mi][1],
                            bf[nxt][mi][2], bf[nxt][mi][3],
                            bB + (uint32_t)mi * (16 * PITCHB)
                               + (uint32_t)(ks + 1) * 32);
                mma16(acc[mi][4], af[ap], bf[cur][2][0], bf[cur][2][2]);
                mma16(acc[mi][5], af[ap], bf[cur][2][1], bf[cur][2][3]);
                mma16(acc[mi][6], af[ap], bf[cur][3][0], bf[cur][3][2]);
                mma16(acc[mi][7], af[ap], bf[cur][3][1], bf[cur][3][3]);
            }
        }
        CP_COMMIT();                    // one group per iteration (maybe empty)
        agp += TKC;
        bgp += TKC;
        slot = (slot == NS - 1) ? 0 : slot + 1;
        pslot = (pslot == NS - 1) ? 0 : pslot + 1;
    }

    // ---- epilogue -----------------------------------------------------------
#pragma unroll
    for (int mi = 0; mi < 4; mi++) {
        const int r0 = m0 + wm + mi * 16 + g;
        const int r1 = r0 + 8;
#pragma unroll
        for (int ni = 0; ni < 8; ni++) {
            const int cc = n0 + wn + ni * 8 + 2 * c;
            if (STORE_HALF_RELU) {
                __half* C = (__half*)Cg_;
                __half2 v0 = __floats2half2_rn(fmaxf(acc[mi][ni][0], 0.0f),
                                               fmaxf(acc[mi][ni][1], 0.0f));
                __half2 v1 = __floats2half2_rn(fmaxf(acc[mi][ni][2], 0.0f),
                                               fmaxf(acc[mi][ni][3], 0.0f));
                *(__half2*)(C + (size_t)r0 * NGLOB + cc) = v0;
                *(__half2*)(C + (size_t)r1 * NGLOB + cc) = v1;
            } else {
                float* C = (float*)Cg_;
                *(float2*)(C + (size_t)r0 * NGLOB + cc) =
                    make_float2(acc[mi][ni][0], acc[mi][ni][1]);
                *(float2*)(C + (size_t)r1 * NGLOB + cc) =
                    make_float2(acc[mi][ni][2], acc[mi][ni][3]);
            }
        }
    }
}

// ---------------------------------------------------------------------------
// Weight merge: Wm = f16_rn(W + 0.25 * B[a] @ A[a]),  W:[OUT,IN] row-major
// ---------------------------------------------------------------------------
__global__ void merge_w(const float* __restrict__ W, const float* __restrict__ A,
                        const float* __restrict__ Bm, const int* __restrict__ aid,
                        __half* __restrict__ Wm, int OUT, int IN)
{
    const int in4 = IN >> 2;
    const int i = blockIdx.x * blockDim.x + threadIdx.x;
    if (i >= OUT * in4) return;
    const int f = i / in4;
    const int d = (i - f * in4) << 2;
    const int a = aid[0];

    const float* Aa = A + (size_t)a * RANKL * IN;
    const float* Ba = Bm + (size_t)a * OUT * RANKL + (size_t)f * RANKL;
    const float b0 = Ba[0] * 0.25f, b1 = Ba[1] * 0.25f,
                b2 = Ba[2] * 0.25f, b3 = Ba[3] * 0.25f;

    float4 w = ((const float4*)W)[i];
    const float4 a0 = *(const float4*)(Aa + 0 * (size_t)IN + d);
    const float4 a1 = *(const float4*)(Aa + 1 * (size_t)IN + d);
    const float4 a2 = *(const float4*)(Aa + 2 * (size_t)IN + d);
    const float4 a3 = *(const float4*)(Aa + 3 * (size_t)IN + d);

    __half2 lo = __floats2half2_rn(w.x + b0 * a0.x + b1 * a1.x + b2 * a2.x + b3 * a3.x,
                                   w.y + b0 * a0.y + b1 * a1.y + b2 * a2.y + b3 * a3.y);
    __half2 hi = __floats2half2_rn(w.z + b0 * a0.z + b1 * a1.z + b2 * a2.z + b3 * a3.z,
                                   w.w + b0 * a0.w + b1 * a1.w + b2 * a2.w + b3 * a3.w);
    __half2* dst = (__half2*)(Wm + (size_t)i * 4);
    dst[0] = lo;
    dst[1] = hi;
}

// ---------------------------------------------------------------------------
// Activation pre-round: xh = f16_rn(x)
// ---------------------------------------------------------------------------
__global__ void to_half(const float4* __restrict__ in, __half* __restrict__ out,
                        int n4)
{
    const int i = blockIdx.x * blockDim.x + threadIdx.x;
    if (i >= n4) return;
    float4 v = in[i];
    __half2* dst = (__half2*)(out + (size_t)i * 4);
    dst[0] = __floats2half2_rn(v.x, v.y);
    dst[1] = __floats2half2_rn(v.z, v.w);
}

// ---------------------------------------------------------------------------
// Launch
// ---------------------------------------------------------------------------
extern "C" void kernel_launch(void* const* d_in, const int* in_sizes, int n_in,
                              void* d_out, int out_size)
{
    const float* x   = (const float*)d_in[0];
    const float* W1  = (const float*)d_in[1];
    const float* A1  = (const float*)d_in[2];
    const float* B1  = (const float*)d_in[3];
    const float* W2  = (const float*)d_in[4];
    const float* A2  = (const float*)d_in[5];
    const float* B2  = (const float*)d_in[6];
    const int*   aid = (const int*)d_in[7];
    float* out = (float*)d_out;

    __half *xh, *h, *w1h, *w2h;
    cudaGetSymbolAddress((void**)&xh,  g_xh);
    cudaGetSymbolAddress((void**)&h,   g_h);
    cudaGetSymbolAddress((void**)&w1h, g_w1h);
    cudaGetSymbolAddress((void**)&w2h, g_w2h);

    cudaFuncSetAttribute((gemm_f16<true, DMODEL, DFF>),
                         cudaFuncAttributeMaxDynamicSharedMemorySize, SMEM_TOTAL);
    cudaFuncSetAttribute((gemm_f16<false, DFF, DMODEL>),
                         cudaFuncAttributeMaxDynamicSharedMemorySize, SMEM_TOTAL);

    // 1) x -> fp16
    const int n4x = TOK * DMODEL / 4;
    to_half<<<(n4x + 255) / 256, 256>>>((const float4*)x, xh, n4x);

    // 2) fold LoRA into weights, round to fp16
    const int n4w = DFF * DMODEL / 4;
    merge_w<<<(n4w + 255) / 256, 256>>>(W1, A1, B1, aid, w1h, DFF, DMODEL);
    merge_w<<<(n4w + 255) / 256, 256>>>(W2, A2, B2, aid, w2h, DMODEL, DFF);

    // 3) h = f16(relu(xh @ w1h^T))     M=16384, N=4096, K=1024
    dim3 g1(DFF / TN, TOK / TM);
    gemm_f16<true, DMODEL, DFF><<<g1, 128, SMEM_TOTAL>>>(xh, w1h, (void*)h);

    // 4) out = h @ w2h^T  (fp32)       M=16384, N=1024, K=4096
    dim3 g2(DMODEL / TN, TOK / TM);
    gemm_f16<false, DFF, DMODEL><<<g2, 128, SMEM_TOTAL>>>(h, w2h, (void*)out);
}